// round 1
// baseline (speedup 1.0000x reference)
#include <cuda_runtime.h>
#include <cuda_bf16.h>
#include <math.h>

// ---------------- problem constants ----------------
#define Bb 4
#define NN_ 1024
#define CC 512
#define HH 32
#define WW 32
#define HEADS 8
#define HD 64
#define WSZ 8
#define BH (Bb*HEADS)          // 32
#define ROWS (Bb*NN_)          // 4096

// ---------------- scratch (no allocation allowed) ----------------
__device__ float g_Q[ROWS*CC];
__device__ float g_K[ROWS*CC];
__device__ float g_V[ROWS*CC];
__device__ float g_H[ROWS*CC];
__device__ float g_Att[ROWS*CC];
__device__ float g_coords[BH*NN_*2];
__device__ float g_Ks[BH*NN_*HD];
__device__ float g_Vs[BH*NN_*HD];
__device__ float g_S[(long long)BH*NN_*NN_];   // 128 MB scores
__device__ float g_Mb[NN_*64];
__device__ float g_Bias[NN_*NN_];

// ---------------- generic batched SGEMM ----------------
// C[m,n] = scale * sum_k A[m,k]*B(n,k) + biasVec[n] + bias2d[m,n]
// BNT=true : B row-major [N,K]  (B[n*ldb+k])   -- "NT"
// BNT=false: B row-major [K,N]  (B[k*ldb+n])   -- "NN"
// batch offsets: off = (z/group)*S1 + (z%group)*S2 per operand.
template<int BM, int BN, int BK, bool BNT>
__global__ void sgemm_kernel(const float* __restrict__ A,
                             const float* __restrict__ B,
                             const float* __restrict__ biasVec,
                             const float* __restrict__ bias2d,
                             float* __restrict__ C,
                             int M, int Nn, int K,
                             int lda, int ldb, int ldc,
                             float scale, int group,
                             long long aS1, long long aS2,
                             long long bS1, long long bS2,
                             long long cS1, long long cS2)
{
    constexpr int TM = BM / 16;
    constexpr int TN = BN / 16;
    __shared__ float As[BK][BM];
    __shared__ float Bs[BK][BN];

    int z = blockIdx.z;
    A += (long long)(z / group) * aS1 + (long long)(z % group) * aS2;
    B += (long long)(z / group) * bS1 + (long long)(z % group) * bS2;
    C += (long long)(z / group) * cS1 + (long long)(z % group) * cS2;

    const int bm = blockIdx.y * BM;
    const int bn = blockIdx.x * BN;
    const int tid = threadIdx.x;          // 256 threads
    const int tr = tid / 16;
    const int tc = tid % 16;

    float acc[TM][TN];
    #pragma unroll
    for (int i = 0; i < TM; i++)
        #pragma unroll
        for (int j = 0; j < TN; j++) acc[i][j] = 0.f;

    for (int k0 = 0; k0 < K; k0 += BK) {
        // --- load A tile (BM x BK), K-contiguous, store transposed ---
        #pragma unroll
        for (int i = tid; i < BM * BK / 4; i += 256) {
            int row = i / (BK / 4);
            int kq  = (i % (BK / 4)) * 4;
            float4 v = *(const float4*)&A[(long)(bm + row) * lda + k0 + kq];
            As[kq + 0][row] = v.x;
            As[kq + 1][row] = v.y;
            As[kq + 2][row] = v.z;
            As[kq + 3][row] = v.w;
        }
        // --- load B tile ---
        if (BNT) {
            #pragma unroll
            for (int i = tid; i < BN * BK / 4; i += 256) {
                int row = i / (BK / 4);
                int kq  = (i % (BK / 4)) * 4;
                float4 v = *(const float4*)&B[(long)(bn + row) * ldb + k0 + kq];
                Bs[kq + 0][row] = v.x;
                Bs[kq + 1][row] = v.y;
                Bs[kq + 2][row] = v.z;
                Bs[kq + 3][row] = v.w;
            }
        } else {
            #pragma unroll
            for (int i = tid; i < BK * BN / 4; i += 256) {
                int kk = i / (BN / 4);
                int nq = (i % (BN / 4)) * 4;
                float4 v = *(const float4*)&B[(long)(k0 + kk) * ldb + bn + nq];
                *(float4*)&Bs[kk][nq] = v;
            }
        }
        __syncthreads();

        #pragma unroll
        for (int k = 0; k < BK; k++) {
            float ar[TM], br[TN];
            #pragma unroll
            for (int i = 0; i < TM; i++) ar[i] = As[k][tr * TM + i];
            #pragma unroll
            for (int j = 0; j < TN; j++) br[j] = Bs[k][tc * TN + j];
            #pragma unroll
            for (int i = 0; i < TM; i++)
                #pragma unroll
                for (int j = 0; j < TN; j++)
                    acc[i][j] += ar[i] * br[j];
        }
        __syncthreads();
    }

    // --- epilogue ---
    #pragma unroll
    for (int i = 0; i < TM; i++) {
        int m = bm + tr * TM + i;
        #pragma unroll
        for (int j = 0; j < TN; j++) {
            int n = bn + tc * TN + j;
            float v = acc[i][j] * scale;
            if (biasVec) v += biasVec[n];
            if (bias2d)  v += bias2d[(long)m * Nn + n];
            C[(long)m * ldc + n] = v;
        }
    }
}

// ---------------- depthwise 5x5 conv + exact GELU ----------------
__global__ void dwconv_gelu_kernel(const float* __restrict__ x,
                                   const float* __restrict__ dw_w,
                                   const float* __restrict__ dw_b,
                                   float* __restrict__ Hb)
{
    int c = threadIdx.x;                 // 512
    long bp = blockIdx.x;                // b*1024 + pix
    int b = (int)(bp >> 10);
    int pix = (int)(bp & 1023);
    int y = pix >> 5, xx = pix & 31;
    const float* w = dw_w + c * 25;
    const float* xb = x + (long)b * NN_ * CC;
    float s = dw_b[c];
    #pragma unroll
    for (int ky = 0; ky < 5; ky++) {
        int yy = y + ky - 2;
        if (yy < 0 || yy > 31) continue;
        #pragma unroll
        for (int kx = 0; kx < 5; kx++) {
            int xc = xx + kx - 2;
            if (xc < 0 || xc > 31) continue;
            s += xb[(long)(yy * 32 + xc) * CC + c] * w[ky * 5 + kx];
        }
    }
    float g = 0.5f * s * (1.0f + erff(s * 0.70710678118654752f));
    Hb[bp * CC + c] = g;
}

// ---------------- offset 1x1 + tanh + coords ----------------
__global__ void offset_kernel(const float* __restrict__ Hb,
                              const float* __restrict__ off_w,
                              float* __restrict__ coords)
{
    __shared__ float red[16][16];        // [warp][k]
    int tid = threadIdx.x;               // 512
    int wid = tid >> 5;
    long bp = blockIdx.x;
    float hv = Hb[bp * CC + tid];
    #pragma unroll
    for (int k = 0; k < 16; k++) {
        float p = hv * off_w[k * CC + tid];
        #pragma unroll
        for (int o = 16; o; o >>= 1) p += __shfl_xor_sync(0xffffffffu, p, o);
        if ((tid & 31) == 0) red[wid][k] = p;
    }
    __syncthreads();
    if (tid < 16) {
        float s = 0.f;
        #pragma unroll
        for (int w2 = 0; w2 < 16; w2++) s += red[w2][tid];
        int b = (int)(bp >> 10), pix = (int)(bp & 1023);
        int h = tid >> 1, comp = tid & 1;
        float off = tanhf(s) * 2.0f;
        int y = pix >> 5, xx = pix & 31;
        float base = (comp == 0) ? (-1.0f + 2.0f * xx / 31.0f)
                                 : (-1.0f + 2.0f * y  / 31.0f);
        float sv = fminf(1.0f, fmaxf(-1.0f, base + off));
        float pc = (sv + 1.0f) * 16.0f - 0.5f;   // pixel coords, Wi=Hi=32
        coords[(((long)b * HEADS + h) * NN_ + pix) * 2 + comp] = pc;
    }
}

// ---------------- bicubic taps (out 1024 <- in 64, PyTorch a=-0.75) ----------------
__device__ __forceinline__ void bicubic_taps(int i, float* w, int* idx)
{
    const float a = -0.75f;
    float src = (i + 0.5f) * (64.0f / 1024.0f) - 0.5f;
    float fl = floorf(src);
    int i0 = (int)fl;
    float t = src - fl;
    #pragma unroll
    for (int k = -1; k <= 2; k++) {
        float d = fabsf(t - (float)k);
        float wk;
        if (d <= 1.0f)      wk = ((a + 2.0f) * d - (a + 3.0f)) * d * d + 1.0f;
        else if (d < 2.0f)  wk = ((a * d - 5.0f * a) * d + 8.0f * a) * d - 4.0f * a;
        else                wk = 0.0f;
        w[k + 1] = wk;
        int ii = i0 + k;
        idx[k + 1] = min(63, max(0, ii));
    }
}

// Mb[i][q] = sum_p M[i][p] * bias0[p][q],  bias0 via rel-pos index lookup
__global__ void bias_mb_kernel(const float* __restrict__ table, float* __restrict__ Mb)
{
    int gid = blockIdx.x * 256 + threadIdx.x;   // 1024*64
    int i = gid >> 6, q = gid & 63;
    float w[4]; int idx[4];
    bicubic_taps(i, w, idx);
    float s = 0.f;
    #pragma unroll
    for (int a = 0; a < 4; a++) {
        int p = idx[a];
        int rpi = ((p >> 3) - (q >> 3) + 7) * 15 + ((p & 7) - (q & 7) + 7);
        s += w[a] * table[rpi];
    }
    Mb[gid] = s;
}

// Bias[i][j] = sum_a w_j[a] * Mb[i][idx_j[a]]
__global__ void bias_full_kernel(const float* __restrict__ Mb, float* __restrict__ Bias)
{
    long gid = (long)blockIdx.x * 256 + threadIdx.x;  // 1M
    int i = (int)(gid >> 10), j = (int)(gid & 1023);
    float w[4]; int idx[4];
    bicubic_taps(j, w, idx);
    const float* m = Mb + (long)i * 64;
    float s = 0.f;
    #pragma unroll
    for (int a = 0; a < 4; a++) s += w[a] * m[idx[a]];
    Bias[gid] = s;
}

// ---------------- bilinear grid sample of K and V ----------------
__global__ void grid_sample_kernel(const float* __restrict__ Kb,
                                   const float* __restrict__ Vb,
                                   const float* __restrict__ coords,
                                   float* __restrict__ Ks,
                                   float* __restrict__ Vs)
{
    int t = threadIdx.x;        // 256 = 4 pixels x 64 d
    int d = t & 63;
    int local = t >> 6;
    long gp = (long)blockIdx.x * 4 + local;     // bh*1024 + pix
    int bh = (int)(gp >> 10);
    int pix = (int)(gp & 1023);
    int b = bh >> 3, h = bh & 7;

    float gx = coords[gp * 2 + 0];
    float gy = coords[gp * 2 + 1];
    float x0f = floorf(gx), y0f = floorf(gy);
    int x0 = (int)x0f, y0 = (int)y0f;
    float tx = gx - x0f, ty = gy - y0f;

    const float* Kc = Kb + ((long)b * NN_) * CC + h * HD + d;
    const float* Vc = Vb + ((long)b * NN_) * CC + h * HD + d;

    float ak = 0.f, av = 0.f;
    #pragma unroll
    for (int dy = 0; dy < 2; dy++) {
        int yi = y0 + dy;
        float wy = (dy == 0) ? (1.0f - ty) : ty;
        #pragma unroll
        for (int dx = 0; dx < 2; dx++) {
            int xi = x0 + dx;
            float wx = (dx == 0) ? (1.0f - tx) : tx;
            if (xi >= 0 && xi < 32 && yi >= 0 && yi < 32) {
                long o = (long)(yi * 32 + xi) * CC;
                float w = wx * wy;
                ak += w * Kc[o];
                av += w * Vc[o];
            }
        }
    }
    long oo = ((long)bh * NN_ + pix) * HD + d;
    Ks[oo] = ak;
    Vs[oo] = av;
}

// ---------------- softmax (one block per row of S) ----------------
__global__ void softmax_kernel(float* __restrict__ S)
{
    __shared__ float red[8];
    __shared__ float red2[8];
    long row = blockIdx.x;
    float* p = S + row * NN_;
    int tid = threadIdx.x;     // 256
    float4 v = ((float4*)p)[tid];
    float m = fmaxf(fmaxf(v.x, v.y), fmaxf(v.z, v.w));
    #pragma unroll
    for (int o = 16; o; o >>= 1) m = fmaxf(m, __shfl_xor_sync(0xffffffffu, m, o));
    if ((tid & 31) == 0) red[tid >> 5] = m;
    __syncthreads();
    float bm = red[0];
    #pragma unroll
    for (int i = 1; i < 8; i++) bm = fmaxf(bm, red[i]);
    v.x = expf(v.x - bm);
    v.y = expf(v.y - bm);
    v.z = expf(v.z - bm);
    v.w = expf(v.w - bm);
    float s = v.x + v.y + v.z + v.w;
    #pragma unroll
    for (int o = 16; o; o >>= 1) s += __shfl_xor_sync(0xffffffffu, s, o);
    if ((tid & 31) == 0) red2[tid >> 5] = s;
    __syncthreads();
    float tot = 0.f;
    #pragma unroll
    for (int i = 0; i < 8; i++) tot += red2[i];
    float inv = 1.0f / tot;
    v.x *= inv; v.y *= inv; v.z *= inv; v.w *= inv;
    ((float4*)p)[tid] = v;
}

// ---------------- launch ----------------
extern "C" void kernel_launch(void* const* d_in, const int* in_sizes, int n_in,
                              void* d_out, int out_size)
{
    const float* x     = (const float*)d_in[0];
    const float* q_w   = (const float*)d_in[1];
    const float* q_b   = (const float*)d_in[2];
    const float* k_w   = (const float*)d_in[3];
    const float* k_b   = (const float*)d_in[4];
    const float* v_w   = (const float*)d_in[5];
    const float* v_b   = (const float*)d_in[6];
    const float* o_w   = (const float*)d_in[7];
    const float* o_b   = (const float*)d_in[8];
    const float* dw_w  = (const float*)d_in[9];
    const float* dw_b  = (const float*)d_in[10];
    const float* off_w = (const float*)d_in[11];
    const float* btab  = (const float*)d_in[12];
    float* out = (float*)d_out;

    float *pQ, *pK, *pV, *pH, *pAtt, *pCo, *pKs, *pVs, *pS, *pMb, *pBias;
    cudaGetSymbolAddress((void**)&pQ,   g_Q);
    cudaGetSymbolAddress((void**)&pK,   g_K);
    cudaGetSymbolAddress((void**)&pV,   g_V);
    cudaGetSymbolAddress((void**)&pH,   g_H);
    cudaGetSymbolAddress((void**)&pAtt, g_Att);
    cudaGetSymbolAddress((void**)&pCo,  g_coords);
    cudaGetSymbolAddress((void**)&pKs,  g_Ks);
    cudaGetSymbolAddress((void**)&pVs,  g_Vs);
    cudaGetSymbolAddress((void**)&pS,   g_S);
    cudaGetSymbolAddress((void**)&pMb,  g_Mb);
    cudaGetSymbolAddress((void**)&pBias,g_Bias);

    dim3 blk(256);

    // Q/K/V projections: [4096,512] x [512,512]^T
    sgemm_kernel<128,128,16,true><<<dim3(4,32,1), blk>>>(
        x, q_w, q_b, nullptr, pQ, ROWS, CC, CC, CC, CC, CC,
        1.0f, 1, 0,0, 0,0, 0,0);
    sgemm_kernel<128,128,16,true><<<dim3(4,32,1), blk>>>(
        x, k_w, k_b, nullptr, pK, ROWS, CC, CC, CC, CC, CC,
        1.0f, 1, 0,0, 0,0, 0,0);
    sgemm_kernel<128,128,16,true><<<dim3(4,32,1), blk>>>(
        x, v_w, v_b, nullptr, pV, ROWS, CC, CC, CC, CC, CC,
        1.0f, 1, 0,0, 0,0, 0,0);

    // offset network
    dwconv_gelu_kernel<<<ROWS, CC>>>(x, dw_w, dw_b, pH);
    offset_kernel<<<ROWS, CC>>>(pH, off_w, pCo);

    // positional bias (bicubic both axes)
    bias_mb_kernel<<<(NN_*64)/256, 256>>>(btab, pMb);
    bias_full_kernel<<<(NN_*NN_)/256, 256>>>(pMb, pBias);

    // deformable sampling of K, V
    grid_sample_kernel<<<(BH*NN_)/4, 256>>>(pK, pV, pCo, pKs, pVs);

    // scores = Q Ks^T / 8 + bias  (batched over 32 (b,h))
    sgemm_kernel<128,128,16,true><<<dim3(8,8,32), blk>>>(
        pQ, pKs, nullptr, pBias, pS,
        NN_, NN_, HD, CC, HD, NN_,
        0.125f, HEADS,
        (long long)NN_*CC, HD,                       // A: b*524288 + h*64
        (long long)HEADS*NN_*HD, (long long)NN_*HD,  // B: bh*65536
        (long long)HEADS*NN_*NN_, (long long)NN_*NN_ // C: bh*1048576
    );

    softmax_kernel<<<BH*NN_, 256>>>(pS);

    // out = P * Vs  (NN: Vs is [K=1024, N=64] n-contiguous)
    sgemm_kernel<64,64,16,false><<<dim3(1,16,32), blk>>>(
        pS, pVs, nullptr, nullptr, pAtt,
        NN_, HD, NN_, NN_, HD, CC,
        1.0f, HEADS,
        (long long)HEADS*NN_*NN_, (long long)NN_*NN_, // A: bh*1048576
        (long long)HEADS*NN_*HD, (long long)NN_*HD,   // B: bh*65536
        (long long)NN_*CC, HD                         // C: b*524288 + h*64
    );

    // output projection -> d_out [B,N,C]
    sgemm_kernel<128,128,16,true><<<dim3(4,32,1), blk>>>(
        pAtt, o_w, o_b, nullptr, out, ROWS, CC, CC, CC, CC, CC,
        1.0f, 1, 0,0, 0,0, 0,0);
}

// round 2
// speedup vs baseline: 1.6618x; 1.6618x over previous
#include <cuda_runtime.h>
#include <cuda_bf16.h>
#include <math.h>

// ---------------- problem constants ----------------
#define Bb 4
#define NN_ 1024
#define CC 512
#define HEADS 8
#define HD 64
#define BH (Bb*HEADS)          // 32
#define ROWS (Bb*NN_)          // 4096

// ---------------- scratch (no allocation allowed) ----------------
__device__ float g_Q[ROWS*CC];
__device__ float g_K[ROWS*CC];
__device__ float g_V[ROWS*CC];
__device__ float g_H[ROWS*CC];
__device__ float g_Att[ROWS*CC];
__device__ float g_coords[BH*NN_*2];
__device__ float g_Ks[BH*NN_*HD];
__device__ float g_Vs[BH*NN_*HD];
__device__ float g_S[(long long)BH*NN_*NN_];   // 128 MB scores
__device__ float g_Mb[NN_*64];
__device__ float g_Bias[NN_*NN_];

// ---------------- tf32 helpers ----------------
__device__ __forceinline__ unsigned f2tf32(float f) {
    unsigned r;
    asm("cvt.rna.tf32.f32 %0, %1;" : "=r"(r) : "f"(f));
    return r;
}

__device__ __forceinline__ void mma_tf32(float c[4],
                                         unsigned a0, unsigned a1, unsigned a2, unsigned a3,
                                         unsigned b0, unsigned b1)
{
    asm("mma.sync.aligned.m16n8k8.row.col.f32.tf32.tf32.f32 "
        "{%0,%1,%2,%3}, {%4,%5,%6,%7}, {%8,%9}, {%0,%1,%2,%3};"
        : "+f"(c[0]), "+f"(c[1]), "+f"(c[2]), "+f"(c[3])
        : "r"(a0), "r"(a1), "r"(a2), "r"(a3), "r"(b0), "r"(b1));
}

// ---------------- tensor-core batched GEMM (tf32) ----------------
// C[m,n] = scale * sum_k A[m,k]*B(n,k) + biasVec[n] + bias2d[m,n]
// BNT=true : B row-major [N,K]  -- "NT"
// BNT=false: B row-major [K,N]  -- "NN"
// Fragment-order SMEM staging:
//   A tile elem (m,k): mt=m/16, kt=k/8, lane=(m%8)*4+(k%4), reg=(m%16)/8 + 2*((k%8)/4)
//   B tile elem (k,n): nt=n/8,  kt=k/8, lane=(n%8)*4+(k%4), reg=(k%8)/4
template<int BM, int BN, bool BNT>
__global__ void tgemm_kernel(const float* __restrict__ A,
                             const float* __restrict__ B,
                             const float* __restrict__ biasVec,
                             const float* __restrict__ bias2d,
                             float* __restrict__ C,
                             int M, int Nn, int K,
                             int lda, int ldb, int ldc,
                             float scale, int group,
                             long long aS1, long long aS2,
                             long long bS1, long long bS2,
                             long long cS1, long long cS2)
{
    constexpr int BK = 32;
    constexpr int KT = BK / 8;           // 4
    constexpr int MT = BM / 16;          // m16 tiles per block
    constexpr int NT = BN / 8;           // n8 tiles per block
    constexpr int MT_W = MT / 2;         // per-warp m tiles (warps 2 x 4)
    constexpr int NT_W = NT / 4;         // per-warp n tiles

    __shared__ unsigned As[MT * KT * 32 * 4];
    __shared__ unsigned Bs[NT * KT * 32 * 2];

    const int z = blockIdx.z;
    A += (long long)(z / group) * aS1 + (long long)(z % group) * aS2;
    B += (long long)(z / group) * bS1 + (long long)(z % group) * bS2;
    C += (long long)(z / group) * cS1 + (long long)(z % group) * cS2;

    const int bm = blockIdx.y * BM;
    const int bn = blockIdx.x * BN;
    const int tid = threadIdx.x;         // 256
    const int warp = tid >> 5;
    const int lane = tid & 31;
    const int warp_m = warp >> 2;        // 0..1
    const int warp_n = warp & 3;         // 0..3

    float acc[MT_W][NT_W][4];
    #pragma unroll
    for (int i = 0; i < MT_W; i++)
        #pragma unroll
        for (int j = 0; j < NT_W; j++)
            #pragma unroll
            for (int r = 0; r < 4; r++) acc[i][j][r] = 0.f;

    for (int k0 = 0; k0 < K; k0 += BK) {
        // ---- stage A (BM x 32) into fragment order ----
        #pragma unroll
        for (int t = 0; t < BM / 32; t++) {
            int i = tid + t * 256;
            int row = i >> 3;                 // 0..BM-1
            int kq = (i & 7) * 4;             // 0,4,...,28
            float4 v = *(const float4*)&A[(long)(bm + row) * lda + k0 + kq];
            int mt = row >> 4;
            int kt = kq >> 3;
            int reg = ((row & 15) >> 3) + (((kq & 7) >> 2) << 1);
            int base = ((mt * KT + kt) * 32 + (row & 7) * 4) * 4 + reg;
            As[base + 0]  = f2tf32(v.x);
            As[base + 4]  = f2tf32(v.y);
            As[base + 8]  = f2tf32(v.z);
            As[base + 12] = f2tf32(v.w);
        }
        // ---- stage B ----
        if (BNT) {
            #pragma unroll
            for (int t = 0; t < BN / 32; t++) {
                int i = tid + t * 256;
                int row = i >> 3;             // n local
                int kq = (i & 7) * 4;
                float4 v = *(const float4*)&B[(long)(bn + row) * ldb + k0 + kq];
                int nt = row >> 3;
                int kt = kq >> 3;
                int reg = (kq & 7) >> 2;
                int base = ((nt * KT + kt) * 32 + (row & 7) * 4) * 2 + reg;
                Bs[base + 0] = f2tf32(v.x);
                Bs[base + 2] = f2tf32(v.y);
                Bs[base + 4] = f2tf32(v.z);
                Bs[base + 6] = f2tf32(v.w);
            }
        } else {
            #pragma unroll
            for (int t = 0; t < BN / 32; t++) {
                int i = tid + t * 256;
                int kk = i / (BN / 4);        // 0..31
                int nq = (i % (BN / 4)) * 4;  // n local, mult of 4
                float4 v = *(const float4*)&B[(long)(k0 + kk) * ldb + bn + nq];
                int nt = nq >> 3;
                int kt = kk >> 3;
                int reg = (kk & 7) >> 2;
                int base = ((nt * KT + kt) * 32 + (nq & 7) * 4 + (kk & 3)) * 2 + reg;
                Bs[base + 0]  = f2tf32(v.x);
                Bs[base + 8]  = f2tf32(v.y);
                Bs[base + 16] = f2tf32(v.z);
                Bs[base + 24] = f2tf32(v.w);
            }
        }
        __syncthreads();

        // ---- compute ----
        #pragma unroll
        for (int kt = 0; kt < KT; kt++) {
            uint4 a[MT_W];
            uint2 b[NT_W];
            #pragma unroll
            for (int i = 0; i < MT_W; i++)
                a[i] = *(const uint4*)&As[(((warp_m * MT_W + i) * KT + kt) * 32 + lane) * 4];
            #pragma unroll
            for (int j = 0; j < NT_W; j++)
                b[j] = *(const uint2*)&Bs[(((warp_n * NT_W + j) * KT + kt) * 32 + lane) * 2];
            #pragma unroll
            for (int i = 0; i < MT_W; i++)
                #pragma unroll
                for (int j = 0; j < NT_W; j++)
                    mma_tf32(acc[i][j], a[i].x, a[i].y, a[i].z, a[i].w, b[j].x, b[j].y);
        }
        __syncthreads();
    }

    // ---- epilogue ----
    const int r = lane >> 2;
    const int cpair = (lane & 3) * 2;
    #pragma unroll
    for (int i = 0; i < MT_W; i++) {
        int m0 = bm + warp_m * MT_W * 16 + i * 16 + r;
        #pragma unroll
        for (int j = 0; j < NT_W; j++) {
            int n0 = bn + warp_n * NT_W * 8 + j * 8 + cpair;
            #pragma unroll
            for (int e = 0; e < 4; e++) {
                int m = m0 + (e >> 1) * 8;
                int n = n0 + (e & 1);
                float v = acc[i][j][e] * scale;
                if (biasVec) v += biasVec[n];
                if (bias2d)  v += bias2d[(long)m * Nn + n];
                C[(long)m * ldc + n] = v;
            }
        }
    }
}

// ---------------- depthwise 5x5 conv + exact GELU ----------------
__global__ void dwconv_gelu_kernel(const float* __restrict__ x,
                                   const float* __restrict__ dw_w,
                                   const float* __restrict__ dw_b,
                                   float* __restrict__ Hb)
{
    int c = threadIdx.x;                 // 512
    long bp = blockIdx.x;                // b*1024 + pix
    int b = (int)(bp >> 10);
    int pix = (int)(bp & 1023);
    int y = pix >> 5, xx = pix & 31;
    const float* w = dw_w + c * 25;
    const float* xb = x + (long)b * NN_ * CC;
    float s = dw_b[c];
    #pragma unroll
    for (int ky = 0; ky < 5; ky++) {
        int yy = y + ky - 2;
        if (yy < 0 || yy > 31) continue;
        #pragma unroll
        for (int kx = 0; kx < 5; kx++) {
            int xc = xx + kx - 2;
            if (xc < 0 || xc > 31) continue;
            s += xb[(long)(yy * 32 + xc) * CC + c] * w[ky * 5 + kx];
        }
    }
    float g = 0.5f * s * (1.0f + erff(s * 0.70710678118654752f));
    Hb[bp * CC + c] = g;
}

// ---------------- offset 1x1 + tanh + coords ----------------
__global__ void offset_kernel(const float* __restrict__ Hb,
                              const float* __restrict__ off_w,
                              float* __restrict__ coords)
{
    __shared__ float red[16][16];        // [warp][k]
    int tid = threadIdx.x;               // 512
    int wid = tid >> 5;
    long bp = blockIdx.x;
    float hv = Hb[bp * CC + tid];
    #pragma unroll
    for (int k = 0; k < 16; k++) {
        float p = hv * off_w[k * CC + tid];
        #pragma unroll
        for (int o = 16; o; o >>= 1) p += __shfl_xor_sync(0xffffffffu, p, o);
        if ((tid & 31) == 0) red[wid][k] = p;
    }
    __syncthreads();
    if (tid < 16) {
        float s = 0.f;
        #pragma unroll
        for (int w2 = 0; w2 < 16; w2++) s += red[w2][tid];
        int b = (int)(bp >> 10), pix = (int)(bp & 1023);
        int h = tid >> 1, comp = tid & 1;
        float off = tanhf(s) * 2.0f;
        int y = pix >> 5, xx = pix & 31;
        float base = (comp == 0) ? (-1.0f + 2.0f * xx / 31.0f)
                                 : (-1.0f + 2.0f * y  / 31.0f);
        float sv = fminf(1.0f, fmaxf(-1.0f, base + off));
        float pc = (sv + 1.0f) * 16.0f - 0.5f;   // pixel coords, Wi=Hi=32
        coords[(((long)b * HEADS + h) * NN_ + pix) * 2 + comp] = pc;
    }
}

// ---------------- bicubic taps (out 1024 <- in 64, PyTorch a=-0.75) ----------------
__device__ __forceinline__ void bicubic_taps(int i, float* w, int* idx)
{
    const float a = -0.75f;
    float src = (i + 0.5f) * (64.0f / 1024.0f) - 0.5f;
    float fl = floorf(src);
    int i0 = (int)fl;
    float t = src - fl;
    #pragma unroll
    for (int k = -1; k <= 2; k++) {
        float d = fabsf(t - (float)k);
        float wk;
        if (d <= 1.0f)      wk = ((a + 2.0f) * d - (a + 3.0f)) * d * d + 1.0f;
        else if (d < 2.0f)  wk = ((a * d - 5.0f * a) * d + 8.0f * a) * d - 4.0f * a;
        else                wk = 0.0f;
        w[k + 1] = wk;
        int ii = i0 + k;
        idx[k + 1] = min(63, max(0, ii));
    }
}

// Mb[i][q] = sum_p M[i][p] * bias0[p][q]
__global__ void bias_mb_kernel(const float* __restrict__ table, float* __restrict__ Mb)
{
    int gid = blockIdx.x * 256 + threadIdx.x;   // 1024*64
    int i = gid >> 6, q = gid & 63;
    float w[4]; int idx[4];
    bicubic_taps(i, w, idx);
    float s = 0.f;
    #pragma unroll
    for (int a = 0; a < 4; a++) {
        int p = idx[a];
        int rpi = ((p >> 3) - (q >> 3) + 7) * 15 + ((p & 7) - (q & 7) + 7);
        s += w[a] * table[rpi];
    }
    Mb[gid] = s;
}

// Bias[i][j] = sum_a w_j[a] * Mb[i][idx_j[a]]
__global__ void bias_full_kernel(const float* __restrict__ Mb, float* __restrict__ Bias)
{
    long gid = (long)blockIdx.x * 256 + threadIdx.x;  // 1M
    int i = (int)(gid >> 10), j = (int)(gid & 1023);
    float w[4]; int idx[4];
    bicubic_taps(j, w, idx);
    const float* m = Mb + (long)i * 64;
    float s = 0.f;
    #pragma unroll
    for (int a = 0; a < 4; a++) s += w[a] * m[idx[a]];
    Bias[gid] = s;
}

// ---------------- bilinear grid sample of K and V ----------------
__global__ void grid_sample_kernel(const float* __restrict__ Kb,
                                   const float* __restrict__ Vb,
                                   const float* __restrict__ coords,
                                   float* __restrict__ Ks,
                                   float* __restrict__ Vs)
{
    int t = threadIdx.x;        // 256 = 4 pixels x 64 d
    int d = t & 63;
    int local = t >> 6;
    long gp = (long)blockIdx.x * 4 + local;     // bh*1024 + pix
    int bh = (int)(gp >> 10);
    int b = bh >> 3, h = bh & 7;

    float gx = coords[gp * 2 + 0];
    float gy = coords[gp * 2 + 1];
    float x0f = floorf(gx), y0f = floorf(gy);
    int x0 = (int)x0f, y0 = (int)y0f;
    float tx = gx - x0f, ty = gy - y0f;

    const float* Kc = Kb + ((long)b * NN_) * CC + h * HD + d;
    const float* Vc = Vb + ((long)b * NN_) * CC + h * HD + d;

    float ak = 0.f, av = 0.f;
    #pragma unroll
    for (int dy = 0; dy < 2; dy++) {
        int yi = y0 + dy;
        float wy = (dy == 0) ? (1.0f - ty) : ty;
        #pragma unroll
        for (int dx = 0; dx < 2; dx++) {
            int xi = x0 + dx;
            float wx = (dx == 0) ? (1.0f - tx) : tx;
            if (xi >= 0 && xi < 32 && yi >= 0 && yi < 32) {
                long o = (long)(yi * 32 + xi) * CC;
                float w = wx * wy;
                ak += w * Kc[o];
                av += w * Vc[o];
            }
        }
    }
    long oo = (gp) * HD + d;
    Ks[oo] = ak;
    Vs[oo] = av;
}

// ---------------- softmax (one block per row of S) ----------------
__global__ void softmax_kernel(float* __restrict__ S)
{
    __shared__ float red[8];
    __shared__ float red2[8];
    long row = blockIdx.x;
    float* p = S + row * NN_;
    int tid = threadIdx.x;     // 256
    float4 v = ((float4*)p)[tid];
    float m = fmaxf(fmaxf(v.x, v.y), fmaxf(v.z, v.w));
    #pragma unroll
    for (int o = 16; o; o >>= 1) m = fmaxf(m, __shfl_xor_sync(0xffffffffu, m, o));
    if ((tid & 31) == 0) red[tid >> 5] = m;
    __syncthreads();
    float bm = red[0];
    #pragma unroll
    for (int i = 1; i < 8; i++) bm = fmaxf(bm, red[i]);
    v.x = expf(v.x - bm);
    v.y = expf(v.y - bm);
    v.z = expf(v.z - bm);
    v.w = expf(v.w - bm);
    float s = v.x + v.y + v.z + v.w;
    #pragma unroll
    for (int o = 16; o; o >>= 1) s += __shfl_xor_sync(0xffffffffu, s, o);
    if ((tid & 31) == 0) red2[tid >> 5] = s;
    __syncthreads();
    float tot = 0.f;
    #pragma unroll
    for (int i = 0; i < 8; i++) tot += red2[i];
    float inv = 1.0f / tot;
    v.x *= inv; v.y *= inv; v.z *= inv; v.w *= inv;
    ((float4*)p)[tid] = v;
}

// ---------------- launch ----------------
extern "C" void kernel_launch(void* const* d_in, const int* in_sizes, int n_in,
                              void* d_out, int out_size)
{
    const float* x     = (const float*)d_in[0];
    const float* q_w   = (const float*)d_in[1];
    const float* q_b   = (const float*)d_in[2];
    const float* k_w   = (const float*)d_in[3];
    const float* k_b   = (const float*)d_in[4];
    const float* v_w   = (const float*)d_in[5];
    const float* v_b   = (const float*)d_in[6];
    const float* o_w   = (const float*)d_in[7];
    const float* o_b   = (const float*)d_in[8];
    const float* dw_w  = (const float*)d_in[9];
    const float* dw_b  = (const float*)d_in[10];
    const float* off_w = (const float*)d_in[11];
    const float* btab  = (const float*)d_in[12];
    float* out = (float*)d_out;

    float *pQ, *pK, *pV, *pH, *pAtt, *pCo, *pKs, *pVs, *pS, *pMb, *pBias;
    cudaGetSymbolAddress((void**)&pQ,   g_Q);
    cudaGetSymbolAddress((void**)&pK,   g_K);
    cudaGetSymbolAddress((void**)&pV,   g_V);
    cudaGetSymbolAddress((void**)&pH,   g_H);
    cudaGetSymbolAddress((void**)&pAtt, g_Att);
    cudaGetSymbolAddress((void**)&pCo,  g_coords);
    cudaGetSymbolAddress((void**)&pKs,  g_Ks);
    cudaGetSymbolAddress((void**)&pVs,  g_Vs);
    cudaGetSymbolAddress((void**)&pS,   g_S);
    cudaGetSymbolAddress((void**)&pMb,  g_Mb);
    cudaGetSymbolAddress((void**)&pBias,g_Bias);

    dim3 blk(256);

    // Q/K/V projections: [4096,512] x [512,512]^T  (NT, tf32 tensor cores)
    tgemm_kernel<128,128,true><<<dim3(4,32,1), blk>>>(
        x, q_w, q_b, nullptr, pQ, ROWS, CC, CC, CC, CC, CC,
        1.0f, 1, 0,0, 0,0, 0,0);
    tgemm_kernel<128,128,true><<<dim3(4,32,1), blk>>>(
        x, k_w, k_b, nullptr, pK, ROWS, CC, CC, CC, CC, CC,
        1.0f, 1, 0,0, 0,0, 0,0);
    tgemm_kernel<128,128,true><<<dim3(4,32,1), blk>>>(
        x, v_w, v_b, nullptr, pV, ROWS, CC, CC, CC, CC, CC,
        1.0f, 1, 0,0, 0,0, 0,0);

    // offset network
    dwconv_gelu_kernel<<<ROWS, CC>>>(x, dw_w, dw_b, pH);
    offset_kernel<<<ROWS, CC>>>(pH, off_w, pCo);

    // positional bias (bicubic both axes)
    bias_mb_kernel<<<(NN_*64)/256, 256>>>(btab, pMb);
    bias_full_kernel<<<(NN_*NN_)/256, 256>>>(pMb, pBias);

    // deformable sampling of K, V
    grid_sample_kernel<<<(BH*NN_)/4, 256>>>(pK, pV, pCo, pKs, pVs);

    // scores = Q Ks^T / 8 + bias  (batched over 32 (b,h))
    tgemm_kernel<128,128,true><<<dim3(8,8,32), blk>>>(
        pQ, pKs, nullptr, pBias, pS,
        NN_, NN_, HD, CC, HD, NN_,
        0.125f, HEADS,
        (long long)NN_*CC, HD,
        (long long)HEADS*NN_*HD, (long long)NN_*HD,
        (long long)HEADS*NN_*NN_, (long long)NN_*NN_
    );

    softmax_kernel<<<BH*NN_, 256>>>(pS);

    // out = P * Vs  (NN: Vs is [K=1024, N=64] n-contiguous)
    tgemm_kernel<128,64,false><<<dim3(1,8,32), blk>>>(
        pS, pVs, nullptr, nullptr, pAtt,
        NN_, HD, NN_, NN_, HD, CC,
        1.0f, HEADS,
        (long long)HEADS*NN_*NN_, (long long)NN_*NN_,
        (long long)HEADS*NN_*HD, (long long)NN_*HD,
        (long long)NN_*CC, HD
    );

    // output projection -> d_out [B,N,C]
    tgemm_kernel<128,128,true><<<dim3(4,32,1), blk>>>(
        pAtt, o_w, o_b, nullptr, out, ROWS, CC, CC, CC, CC, CC,
        1.0f, 1, 0,0, 0,0, 0,0);
}

// round 3
// speedup vs baseline: 2.6416x; 1.5896x over previous
#include <cuda_runtime.h>
#include <cuda_bf16.h>
#include <math.h>

// ---------------- problem constants ----------------
#define Bb 4
#define NN_ 1024
#define CC 512
#define HEADS 8
#define HD 64
#define BH (Bb*HEADS)          // 32
#define ROWS (Bb*NN_)          // 4096

// ---------------- scratch (no allocation allowed) ----------------
__device__ float g_Q[ROWS*CC];
__device__ float g_K[ROWS*CC];
__device__ float g_V[ROWS*CC];
__device__ float g_Att[ROWS*CC];
__device__ float g_coords[BH*NN_*2];
__device__ float g_Ks[BH*NN_*HD];
__device__ float g_Vs[BH*NN_*HD];
__device__ float g_Mb[NN_*64];
__device__ float g_Bias[NN_*NN_];

// ---------------- tf32 helpers ----------------
__device__ __forceinline__ unsigned f2tf32(float f) {
    unsigned r;
    asm("cvt.rna.tf32.f32 %0, %1;" : "=r"(r) : "f"(f));
    return r;
}

__device__ __forceinline__ void mma_tf32(float c[4],
                                         unsigned a0, unsigned a1, unsigned a2, unsigned a3,
                                         unsigned b0, unsigned b1)
{
    asm("mma.sync.aligned.m16n8k8.row.col.f32.tf32.tf32.f32 "
        "{%0,%1,%2,%3}, {%4,%5,%6,%7}, {%8,%9}, {%0,%1,%2,%3};"
        : "+f"(c[0]), "+f"(c[1]), "+f"(c[2]), "+f"(c[3])
        : "r"(a0), "r"(a1), "r"(a2), "r"(a3), "r"(b0), "r"(b1));
}

// ---------------- tensor-core GEMM device body (tf32) ----------------
// C[m,n] = scale * sum_k A[m,k]*B(n,k) + biasVec[n] + bias2d[m,n]
// BNT=true : B row-major [N,K] ; BNT=false: B row-major [K,N]
template<int BM, int BN, bool BNT>
__device__ __forceinline__ void tgemm_dev(const float* __restrict__ A,
                                          const float* __restrict__ B,
                                          const float* __restrict__ biasVec,
                                          const float* __restrict__ bias2d,
                                          float* __restrict__ C,
                                          int M, int Nn, int K,
                                          int lda, int ldb, int ldc, float scale)
{
    constexpr int BK = 32;
    constexpr int KT = BK / 8;           // 4
    constexpr int MT = BM / 16;
    constexpr int NT = BN / 8;
    constexpr int MT_W = MT / 2;
    constexpr int NT_W = NT / 4;

    __shared__ unsigned As[MT * KT * 32 * 4];
    __shared__ unsigned Bs[NT * KT * 32 * 2];

    const int bm = blockIdx.y * BM;
    const int bn = blockIdx.x * BN;
    const int tid = threadIdx.x;         // 256
    const int warp = tid >> 5;
    const int lane = tid & 31;
    const int warp_m = warp >> 2;
    const int warp_n = warp & 3;

    float acc[MT_W][NT_W][4];
    #pragma unroll
    for (int i = 0; i < MT_W; i++)
        #pragma unroll
        for (int j = 0; j < NT_W; j++)
            #pragma unroll
            for (int r = 0; r < 4; r++) acc[i][j][r] = 0.f;

    for (int k0 = 0; k0 < K; k0 += BK) {
        #pragma unroll
        for (int t = 0; t < BM / 32; t++) {
            int i = tid + t * 256;
            int row = i >> 3;
            int kq = (i & 7) * 4;
            float4 v = *(const float4*)&A[(long)(bm + row) * lda + k0 + kq];
            int mt = row >> 4;
            int kt = kq >> 3;
            int reg = ((row & 15) >> 3) + (((kq & 7) >> 2) << 1);
            int base = ((mt * KT + kt) * 32 + (row & 7) * 4) * 4 + reg;
            As[base + 0]  = f2tf32(v.x);
            As[base + 4]  = f2tf32(v.y);
            As[base + 8]  = f2tf32(v.z);
            As[base + 12] = f2tf32(v.w);
        }
        if (BNT) {
            #pragma unroll
            for (int t = 0; t < BN / 32; t++) {
                int i = tid + t * 256;
                int row = i >> 3;
                int kq = (i & 7) * 4;
                float4 v = *(const float4*)&B[(long)(bn + row) * ldb + k0 + kq];
                int nt = row >> 3;
                int kt = kq >> 3;
                int reg = (kq & 7) >> 2;
                int base = ((nt * KT + kt) * 32 + (row & 7) * 4) * 2 + reg;
                Bs[base + 0] = f2tf32(v.x);
                Bs[base + 2] = f2tf32(v.y);
                Bs[base + 4] = f2tf32(v.z);
                Bs[base + 6] = f2tf32(v.w);
            }
        } else {
            #pragma unroll
            for (int t = 0; t < BN / 32; t++) {
                int i = tid + t * 256;
                int kk = i / (BN / 4);
                int nq = (i % (BN / 4)) * 4;
                float4 v = *(const float4*)&B[(long)(k0 + kk) * ldb + bn + nq];
                int nt = nq >> 3;
                int kt = kk >> 3;
                int reg = (kk & 7) >> 2;
                int base = ((nt * KT + kt) * 32 + (nq & 7) * 4 + (kk & 3)) * 2 + reg;
                Bs[base + 0]  = f2tf32(v.x);
                Bs[base + 8]  = f2tf32(v.y);
                Bs[base + 16] = f2tf32(v.z);
                Bs[base + 24] = f2tf32(v.w);
            }
        }
        __syncthreads();

        #pragma unroll
        for (int kt = 0; kt < KT; kt++) {
            uint4 a[MT_W];
            uint2 b[NT_W];
            #pragma unroll
            for (int i = 0; i < MT_W; i++)
                a[i] = *(const uint4*)&As[(((warp_m * MT_W + i) * KT + kt) * 32 + lane) * 4];
            #pragma unroll
            for (int j = 0; j < NT_W; j++)
                b[j] = *(const uint2*)&Bs[(((warp_n * NT_W + j) * KT + kt) * 32 + lane) * 2];
            #pragma unroll
            for (int i = 0; i < MT_W; i++)
                #pragma unroll
                for (int j = 0; j < NT_W; j++)
                    mma_tf32(acc[i][j], a[i].x, a[i].y, a[i].z, a[i].w, b[j].x, b[j].y);
        }
        __syncthreads();
    }

    const int r = lane >> 2;
    const int cpair = (lane & 3) * 2;
    #pragma unroll
    for (int i = 0; i < MT_W; i++) {
        int m0 = bm + warp_m * MT_W * 16 + i * 16 + r;
        #pragma unroll
        for (int j = 0; j < NT_W; j++) {
            int n0 = bn + warp_n * NT_W * 8 + j * 8 + cpair;
            #pragma unroll
            for (int e = 0; e < 4; e++) {
                int m = m0 + (e >> 1) * 8;
                int n = n0 + (e & 1);
                float v = acc[i][j][e] * scale;
                if (biasVec) v += biasVec[n];
                if (bias2d)  v += bias2d[(long)m * Nn + n];
                C[(long)m * ldc + n] = v;
            }
        }
    }
}

// generic single-matrix GEMM
template<int BM, int BN, bool BNT>
__global__ void tgemm_kernel(const float* __restrict__ A,
                             const float* __restrict__ B,
                             const float* __restrict__ biasVec,
                             float* __restrict__ C,
                             int M, int Nn, int K,
                             int lda, int ldb, int ldc, float scale)
{
    tgemm_dev<BM, BN, BNT>(A, B, biasVec, nullptr, C, M, Nn, K, lda, ldb, ldc, scale);
}

// batched Q/K/V projections in one launch (z selects)
__global__ void qkv_kernel(const float* __restrict__ x,
                           const float* __restrict__ qw, const float* __restrict__ kw,
                           const float* __restrict__ vw,
                           const float* __restrict__ qb, const float* __restrict__ kb,
                           const float* __restrict__ vb,
                           float* __restrict__ Q, float* __restrict__ K, float* __restrict__ V)
{
    int z = blockIdx.z;
    const float* B    = (z == 0) ? qw : (z == 1) ? kw : vw;
    const float* bias = (z == 0) ? qb : (z == 1) ? kb : vb;
    float* C          = (z == 0) ? Q  : (z == 1) ? K  : V;
    tgemm_dev<128, 128, true>(x, B, bias, nullptr, C, ROWS, CC, CC, CC, CC, CC, 1.0f);
}

// ---------------- fused flash attention (tf32) ----------------
// grid: (8 row-tiles, 32 bh); block 256 (8 warps x 16 rows)
// dynamic smem: Kf 32KB | Vf 32KB | Pf 72KB
#define SMEM_FLASH (32768 + 32768 + 73728)

__global__ void __launch_bounds__(256, 1) flash_kernel(
    const float* __restrict__ Q, const float* __restrict__ Ks,
    const float* __restrict__ Vs, const float* __restrict__ Bias,
    float* __restrict__ Att)
{
    extern __shared__ unsigned smem[];
    unsigned* Kf = smem;                    // [nt16][kt8][lane][2]
    unsigned* Vf = smem + 8192;             // [nt8][kt16][lane][2]
    float* Pf = (float*)(smem + 16384);     // per warp 2304 floats: [nt16][row16][9]

    const int bh = blockIdx.y;
    const int b = bh >> 3, h = bh & 7;
    const int row0 = blockIdx.x * 128;
    const int tid = threadIdx.x;
    const int warp = tid >> 5, lane = tid & 31;
    const int r = lane >> 2, q = lane & 3;
    float* Pw = Pf + warp * 2304;

    const float* Kbh = Ks + (long)bh * NN_ * HD;
    const float* Vbh = Vs + (long)bh * NN_ * HD;

    // Q fragments, scale 1/8 folded in
    unsigned qf[8][4];
    {
        const float* Qp = Q + (long)(b * NN_ + row0 + warp * 16) * CC + h * HD;
        #pragma unroll
        for (int kt = 0; kt < 8; kt++) {
            qf[kt][0] = f2tf32(0.125f * Qp[(long)r * CC + kt * 8 + q]);
            qf[kt][1] = f2tf32(0.125f * Qp[(long)(r + 8) * CC + kt * 8 + q]);
            qf[kt][2] = f2tf32(0.125f * Qp[(long)r * CC + kt * 8 + q + 4]);
            qf[kt][3] = f2tf32(0.125f * Qp[(long)(r + 8) * CC + kt * 8 + q + 4]);
        }
    }

    float o[8][4];
    #pragma unroll
    for (int i = 0; i < 8; i++)
        #pragma unroll
        for (int e = 0; e < 4; e++) o[i][e] = 0.f;
    float mprev0 = -1e30f, mprev1 = -1e30f, l0 = 0.f, l1 = 0.f;

    for (int j = 0; j < 8; j++) {
        __syncthreads();          // previous iter's mma reads done
        // stage K tile (NT frag, k=hd, KT=8)
        {
            const float* Kt = Kbh + (long)j * 128 * HD;
            #pragma unroll
            for (int t = 0; t < 8; t++) {
                int i = tid + t * 256;
                int row = i >> 4;
                int kq = (i & 15) * 4;
                float4 v = *(const float4*)&Kt[row * 64 + kq];
                int nt = row >> 3, kt = kq >> 3, reg = (kq & 7) >> 2;
                int base = ((nt * 8 + kt) * 32 + (row & 7) * 4) * 2 + reg;
                Kf[base + 0] = f2tf32(v.x);
                Kf[base + 2] = f2tf32(v.y);
                Kf[base + 4] = f2tf32(v.z);
                Kf[base + 6] = f2tf32(v.w);
            }
            const float* Vt = Vbh + (long)j * 128 * HD;
            #pragma unroll
            for (int t = 0; t < 8; t++) {
                int i = tid + t * 256;
                int kk = i >> 4;
                int nq = (i & 15) * 4;
                float4 v = *(const float4*)&Vt[kk * 64 + nq];
                int nt = nq >> 3, kt = kk >> 3, reg = (kk & 7) >> 2;
                int base = ((nt * 16 + kt) * 32 + (nq & 7) * 4 + (kk & 3)) * 2 + reg;
                Vf[base + 0]  = f2tf32(v.x);
                Vf[base + 8]  = f2tf32(v.y);
                Vf[base + 16] = f2tf32(v.z);
                Vf[base + 24] = f2tf32(v.w);
            }
        }
        __syncthreads();

        // ---- S = (Q/8) Ks^T ----
        float sacc[16][4];
        #pragma unroll
        for (int nt = 0; nt < 16; nt++)
            #pragma unroll
            for (int e = 0; e < 4; e++) sacc[nt][e] = 0.f;
        #pragma unroll
        for (int kt = 0; kt < 8; kt++) {
            #pragma unroll
            for (int nt = 0; nt < 16; nt++) {
                uint2 bb = *(const uint2*)&Kf[((nt * 8 + kt) * 32 + lane) * 2];
                mma_tf32(sacc[nt], qf[kt][0], qf[kt][1], qf[kt][2], qf[kt][3], bb.x, bb.y);
            }
        }

        // ---- + bias ----
        const float* Brow0 = Bias + (long)(row0 + warp * 16 + r) * NN_ + j * 128 + 2 * q;
        const float* Brow1 = Brow0 + 8 * NN_;
        #pragma unroll
        for (int nt = 0; nt < 16; nt++) {
            float2 b0 = *(const float2*)&Brow0[nt * 8];
            float2 b1 = *(const float2*)&Brow1[nt * 8];
            sacc[nt][0] += b0.x; sacc[nt][1] += b0.y;
            sacc[nt][2] += b1.x; sacc[nt][3] += b1.y;
        }

        // ---- online softmax ----
        float mx0 = -1e30f, mx1 = -1e30f;
        #pragma unroll
        for (int nt = 0; nt < 16; nt++) {
            mx0 = fmaxf(mx0, fmaxf(sacc[nt][0], sacc[nt][1]));
            mx1 = fmaxf(mx1, fmaxf(sacc[nt][2], sacc[nt][3]));
        }
        mx0 = fmaxf(mx0, __shfl_xor_sync(0xffffffffu, mx0, 1));
        mx0 = fmaxf(mx0, __shfl_xor_sync(0xffffffffu, mx0, 2));
        mx1 = fmaxf(mx1, __shfl_xor_sync(0xffffffffu, mx1, 1));
        mx1 = fmaxf(mx1, __shfl_xor_sync(0xffffffffu, mx1, 2));
        float mn0 = fmaxf(mprev0, mx0), mn1 = fmaxf(mprev1, mx1);
        float a0 = __expf(mprev0 - mn0), a1 = __expf(mprev1 - mn1);
        float s0 = 0.f, s1 = 0.f;
        #pragma unroll
        for (int nt = 0; nt < 16; nt++) {
            float p0 = __expf(sacc[nt][0] - mn0);
            float p1 = __expf(sacc[nt][1] - mn0);
            float p2 = __expf(sacc[nt][2] - mn1);
            float p3 = __expf(sacc[nt][3] - mn1);
            s0 += p0 + p1;
            s1 += p2 + p3;
            float* pp  = Pw + (nt * 16 + r) * 9 + 2 * q;
            float* pp8 = Pw + (nt * 16 + r + 8) * 9 + 2 * q;
            pp[0] = p0; pp[1] = p1;
            pp8[0] = p2; pp8[1] = p3;
        }
        s0 += __shfl_xor_sync(0xffffffffu, s0, 1);
        s0 += __shfl_xor_sync(0xffffffffu, s0, 2);
        s1 += __shfl_xor_sync(0xffffffffu, s1, 1);
        s1 += __shfl_xor_sync(0xffffffffu, s1, 2);
        l0 = l0 * a0 + s0;
        l1 = l1 * a1 + s1;
        mprev0 = mn0; mprev1 = mn1;
        #pragma unroll
        for (int nv = 0; nv < 8; nv++) {
            o[nv][0] *= a0; o[nv][1] *= a0;
            o[nv][2] *= a1; o[nv][3] *= a1;
        }
        __syncwarp();

        // ---- O += P V ----
        #pragma unroll
        for (int kt2 = 0; kt2 < 16; kt2++) {
            unsigned pa0 = f2tf32(Pw[(kt2 * 16 + r) * 9 + q]);
            unsigned pa1 = f2tf32(Pw[(kt2 * 16 + r + 8) * 9 + q]);
            unsigned pa2 = f2tf32(Pw[(kt2 * 16 + r) * 9 + q + 4]);
            unsigned pa3 = f2tf32(Pw[(kt2 * 16 + r + 8) * 9 + q + 4]);
            #pragma unroll
            for (int nv = 0; nv < 8; nv++) {
                uint2 bb = *(const uint2*)&Vf[((nv * 16 + kt2) * 32 + lane) * 2];
                mma_tf32(o[nv], pa0, pa1, pa2, pa3, bb.x, bb.y);
            }
        }
    }

    // ---- normalize + write ----
    float inv0 = 1.0f / l0, inv1 = 1.0f / l1;
    float* Op = Att + (long)(b * NN_ + row0 + warp * 16) * CC + h * HD;
    #pragma unroll
    for (int nv = 0; nv < 8; nv++) {
        int col = nv * 8 + 2 * q;
        float2 v0 = { o[nv][0] * inv0, o[nv][1] * inv0 };
        float2 v1 = { o[nv][2] * inv1, o[nv][3] * inv1 };
        *(float2*)&Op[(long)r * CC + col] = v0;
        *(float2*)&Op[(long)(r + 8) * CC + col] = v1;
    }
}

// ---------------- fused depthwise 5x5 + GELU + offset head ----------------
__global__ void dwoff_kernel(const float* __restrict__ x,
                             const float* __restrict__ dw_w,
                             const float* __restrict__ dw_b,
                             const float* __restrict__ off_w,
                             float* __restrict__ coords)
{
    __shared__ float sh[512];
    int c = threadIdx.x;                 // 512
    int bp = blockIdx.x;
    int b = bp >> 10, pix = bp & 1023;
    int y = pix >> 5, xx = pix & 31;
    const float* w = dw_w + c * 25;
    const float* xb = x + ((long)b * NN_) * CC + c;
    float s = dw_b[c];
    if (y >= 2 && y <= 29 && xx >= 2 && xx <= 29) {
        const float* p = xb + ((y - 2) * 32 + (xx - 2)) * CC;
        #pragma unroll
        for (int ky = 0; ky < 5; ky++)
            #pragma unroll
            for (int kx = 0; kx < 5; kx++)
                s += p[(ky * 32 + kx) * CC] * w[ky * 5 + kx];
    } else {
        #pragma unroll
        for (int ky = 0; ky < 5; ky++) {
            int yy = y + ky - 2;
            if (yy < 0 || yy > 31) continue;
            #pragma unroll
            for (int kx = 0; kx < 5; kx++) {
                int xc = xx + kx - 2;
                if (xc < 0 || xc > 31) continue;
                s += xb[(yy * 32 + xc) * CC] * w[ky * 5 + kx];
            }
        }
    }
    sh[c] = 0.5f * s * (1.0f + erff(s * 0.70710678118654752f));
    __syncthreads();

    int wid = c >> 5, lane = c & 31;     // warp wid handles k = wid (16 of them)
    const float* wrow = off_w + wid * CC;
    float acc = 0.f;
    #pragma unroll
    for (int i = 0; i < 16; i++)
        acc += sh[lane + i * 32] * wrow[lane + i * 32];
    #pragma unroll
    for (int off = 16; off; off >>= 1)
        acc += __shfl_xor_sync(0xffffffffu, acc, off);
    if (lane == 0) {
        int h = wid >> 1, comp = wid & 1;
        float off2 = tanhf(acc) * 2.0f;
        float base = (comp == 0) ? (-1.0f + 2.0f * xx / 31.0f)
                                 : (-1.0f + 2.0f * y  / 31.0f);
        float sv = fminf(1.0f, fmaxf(-1.0f, base + off2));
        float pc = (sv + 1.0f) * 16.0f - 0.5f;
        coords[(((long)b * HEADS + h) * NN_ + pix) * 2 + comp] = pc;
    }
}

// ---------------- bicubic taps ----------------
__device__ __forceinline__ void bicubic_taps(int i, float* w, int* idx)
{
    const float a = -0.75f;
    float src = (i + 0.5f) * (64.0f / 1024.0f) - 0.5f;
    float fl = floorf(src);
    int i0 = (int)fl;
    float t = src - fl;
    #pragma unroll
    for (int k = -1; k <= 2; k++) {
        float d = fabsf(t - (float)k);
        float wk;
        if (d <= 1.0f)      wk = ((a + 2.0f) * d - (a + 3.0f)) * d * d + 1.0f;
        else if (d < 2.0f)  wk = ((a * d - 5.0f * a) * d + 8.0f * a) * d - 4.0f * a;
        else                wk = 0.0f;
        w[k + 1] = wk;
        int ii = i0 + k;
        idx[k + 1] = min(63, max(0, ii));
    }
}

__global__ void bias_mb_kernel(const float* __restrict__ table, float* __restrict__ Mb)
{
    int gid = blockIdx.x * 256 + threadIdx.x;   // 1024*64
    int i = gid >> 6, q = gid & 63;
    float w[4]; int idx[4];
    bicubic_taps(i, w, idx);
    float s = 0.f;
    #pragma unroll
    for (int a = 0; a < 4; a++) {
        int p = idx[a];
        int rpi = ((p >> 3) - (q >> 3) + 7) * 15 + ((p & 7) - (q & 7) + 7);
        s += w[a] * table[rpi];
    }
    Mb[gid] = s;
}

__global__ void bias_full_kernel(const float* __restrict__ Mb, float* __restrict__ Bias)
{
    long gid = (long)blockIdx.x * 256 + threadIdx.x;  // 1M
    int i = (int)(gid >> 10), j = (int)(gid & 1023);
    float w[4]; int idx[4];
    bicubic_taps(j, w, idx);
    const float* m = Mb + (long)i * 64;
    float s = 0.f;
    #pragma unroll
    for (int a = 0; a < 4; a++) s += w[a] * m[idx[a]];
    Bias[gid] = s;
}

// ---------------- bilinear grid sample of K and V ----------------
__global__ void grid_sample_kernel(const float* __restrict__ Kb,
                                   const float* __restrict__ Vb,
                                   const float* __restrict__ coords,
                                   float* __restrict__ Ks,
                                   float* __restrict__ Vs)
{
    int t = threadIdx.x;        // 256 = 4 pixels x 64 d
    int d = t & 63;
    int local = t >> 6;
    long gp = (long)blockIdx.x * 4 + local;     // bh*1024 + pix
    int bh = (int)(gp >> 10);
    int b = bh >> 3, h = bh & 7;

    float gx = coords[gp * 2 + 0];
    float gy = coords[gp * 2 + 1];
    float x0f = floorf(gx), y0f = floorf(gy);
    int x0 = (int)x0f, y0 = (int)y0f;
    float tx = gx - x0f, ty = gy - y0f;

    const float* Kc = Kb + ((long)b * NN_) * CC + h * HD + d;
    const float* Vc = Vb + ((long)b * NN_) * CC + h * HD + d;

    float ak = 0.f, av = 0.f;
    #pragma unroll
    for (int dy = 0; dy < 2; dy++) {
        int yi = y0 + dy;
        float wy = (dy == 0) ? (1.0f - ty) : ty;
        #pragma unroll
        for (int dx = 0; dx < 2; dx++) {
            int xi = x0 + dx;
            float wx = (dx == 0) ? (1.0f - tx) : tx;
            if (xi >= 0 && xi < 32 && yi >= 0 && yi < 32) {
                long o = (long)(yi * 32 + xi) * CC;
                float wgt = wx * wy;
                ak += wgt * Kc[o];
                av += wgt * Vc[o];
            }
        }
    }
    long oo = gp * HD + d;
    Ks[oo] = ak;
    Vs[oo] = av;
}

// ---------------- launch ----------------
extern "C" void kernel_launch(void* const* d_in, const int* in_sizes, int n_in,
                              void* d_out, int out_size)
{
    const float* x     = (const float*)d_in[0];
    const float* q_w   = (const float*)d_in[1];
    const float* q_b   = (const float*)d_in[2];
    const float* k_w   = (const float*)d_in[3];
    const float* k_b   = (const float*)d_in[4];
    const float* v_w   = (const float*)d_in[5];
    const float* v_b   = (const float*)d_in[6];
    const float* o_w   = (const float*)d_in[7];
    const float* o_b   = (const float*)d_in[8];
    const float* dw_w  = (const float*)d_in[9];
    const float* dw_b  = (const float*)d_in[10];
    const float* off_w = (const float*)d_in[11];
    const float* btab  = (const float*)d_in[12];
    float* out = (float*)d_out;

    float *pQ, *pK, *pV, *pAtt, *pCo, *pKs, *pVs, *pMb, *pBias;
    cudaGetSymbolAddress((void**)&pQ,   g_Q);
    cudaGetSymbolAddress((void**)&pK,   g_K);
    cudaGetSymbolAddress((void**)&pV,   g_V);
    cudaGetSymbolAddress((void**)&pAtt, g_Att);
    cudaGetSymbolAddress((void**)&pCo,  g_coords);
    cudaGetSymbolAddress((void**)&pKs,  g_Ks);
    cudaGetSymbolAddress((void**)&pVs,  g_Vs);
    cudaGetSymbolAddress((void**)&pMb,  g_Mb);
    cudaGetSymbolAddress((void**)&pBias,g_Bias);

    static bool attr_done = false;
    if (!attr_done) {
        cudaFuncSetAttribute(flash_kernel,
                             cudaFuncAttributeMaxDynamicSharedMemorySize, SMEM_FLASH);
        attr_done = true;
    }

    dim3 blk(256);

    // Q/K/V projections, batched in z
    qkv_kernel<<<dim3(4, 32, 3), blk>>>(x, q_w, k_w, v_w, q_b, k_b, v_b, pQ, pK, pV);

    // offset network (fused dwconv+gelu+1x1+tanh+coords)
    dwoff_kernel<<<ROWS, CC>>>(x, dw_w, dw_b, off_w, pCo);

    // positional bias (bicubic both axes)
    bias_mb_kernel<<<(NN_*64)/256, 256>>>(btab, pMb);
    bias_full_kernel<<<(NN_*NN_)/256, 256>>>(pMb, pBias);

    // deformable sampling of K, V
    grid_sample_kernel<<<(BH*NN_)/4, 256>>>(pK, pV, pCo, pKs, pVs);

    // fused attention: QK^T/8 + bias -> softmax -> PV
    flash_kernel<<<dim3(8, 32), blk, SMEM_FLASH>>>(pQ, pKs, pVs, pBias, pAtt);

    // output projection -> d_out
    tgemm_kernel<128,128,true><<<dim3(4, 32, 1), blk>>>(
        pAtt, o_w, o_b, out, ROWS, CC, CC, CC, CC, CC, 1.0f);
}